// round 12
// baseline (speedup 1.0000x reference)
#include <cuda_runtime.h>
#include <cuda_fp16.h>
#include <cstdint>
#include <cstddef>

#define NN 4096
#define DM 256
#define NH 8
#define DH 32

#define PRANGE 48.0f
#define RRANGE 2.542f

// ---------------- scratch (device globals; no allocation) ----------------
__device__ __half         g_Attn[(size_t)NH * NN * NN];  // fp16 attn after softmax
__device__ unsigned char  g_Pq_hi[(size_t)NH * NN * NN]; // P u16 fixed-point, hi byte
__device__ unsigned char  g_Pq_lo[(size_t)NH * NN * NN]; // lo byte
__device__ unsigned char  g_Rq_hi[(size_t)NN * NN];      // (rescale(dist)-1)^T u16, hi byte, [p][m]
__device__ unsigned char  g_Rq_lo[(size_t)NN * NN];
__device__ int            g_S1[(size_t)NH * NN];         // rowsum of P16 per score row
__device__ float          g_S[(size_t)NH * NN * NN];     // fp32 scores
__device__ __half g_Qh[(size_t)NN * DM];                 // Q projection fp16 hi/lo
__device__ __half g_Ql[(size_t)NN * DM];
__device__ __half g_Kh[(size_t)NN * DM];
__device__ __half g_Kl[(size_t)NN * DM];
__device__ __half g_VT[(size_t)DM * NN];                 // V^T fp16: g_VT[j][n] = V[n][j]

// ---------------- helpers ----------------
__device__ __forceinline__ uint32_t smem_u32(const void* p) {
    uint32_t a;
    asm("{ .reg .u64 t; cvta.to.shared.u64 t, %1; cvt.u32.u64 %0, t; }" : "=r"(a) : "l"(p));
    return a;
}

__device__ __forceinline__ void ldsm_x4(uint32_t* r, uint32_t addr) {
    asm volatile("ldmatrix.sync.aligned.m8n8.x4.shared.b16 {%0,%1,%2,%3}, [%4];"
                 : "=r"(r[0]), "=r"(r[1]), "=r"(r[2]), "=r"(r[3]) : "r"(addr));
}

__device__ __forceinline__ void mma16816(float* c, const uint32_t* a, const uint32_t* b) {
    asm volatile(
        "mma.sync.aligned.m16n8k16.row.col.f32.f16.f16.f32 "
        "{%0,%1,%2,%3}, {%4,%5,%6,%7}, {%8,%9}, {%0,%1,%2,%3};"
        : "+f"(c[0]), "+f"(c[1]), "+f"(c[2]), "+f"(c[3])
        : "r"(a[0]), "r"(a[1]), "r"(a[2]), "r"(a[3]), "r"(b[0]), "r"(b[1]));
}

__device__ __forceinline__ void mma16832u8(int* c, const uint32_t* a, const uint32_t* b) {
    asm volatile(
        "mma.sync.aligned.m16n8k32.row.col.s32.u8.u8.s32 "
        "{%0,%1,%2,%3}, {%4,%5,%6,%7}, {%8,%9}, {%0,%1,%2,%3};"
        : "+r"(c[0]), "+r"(c[1]), "+r"(c[2]), "+r"(c[3])
        : "r"(a[0]), "r"(a[1]), "r"(a[2]), "r"(a[3]), "r"(b[0]), "r"(b[1]));
}

__device__ __forceinline__ void cp16(uint32_t smem, const void* gmem) {
    asm volatile("cp.async.cg.shared.global [%0], [%1], 16;" :: "r"(smem), "l"(gmem));
}

// ---------------- kernel 1: R' = rescale(dist)-1, transposed, u16->2xu8 ----------------
__global__ void __launch_bounds__(1024) k_rescale(const float* __restrict__ dist) {
    __shared__ float t[32][33];
    const int m0 = blockIdx.y * 32, p0 = blockIdx.x * 32;
    const int tx = threadIdx.x, ty = threadIdx.y;
    float d = dist[(size_t)(m0 + ty) * NN + p0 + tx];
    t[ty][tx] = 3.718281828459045f / (1.0f + __expf(1.0f - d));
    __syncthreads();
    float r = t[tx][ty];  // = R[m0+tx][p0+ty]
    float rp = r - 1.0f;
    unsigned q = (unsigned)fminf(fmaxf(rintf(rp * (65535.0f / RRANGE)), 0.0f), 65535.0f);
    size_t o = (size_t)(p0 + ty) * NN + m0 + tx;
    g_Rq_hi[o] = (unsigned char)(q >> 8);
    g_Rq_lo[o] = (unsigned char)(q & 255u);
}

// ---------------- kernel 2: projections out[n][j] = sum_k X[n][k]*W[j][k] ----------------
// which: 0 -> Q (fp16 hi/lo), 1 -> K (fp16 hi/lo), 2 -> V^T (fp16, transposed store)
__global__ void __launch_bounds__(1024) k_proj(const float* __restrict__ X,
                                               const float* __restrict__ W, int which) {
    __shared__ float Xs[32][33], Ws[32][33];
    const int n0 = blockIdx.y * 32, j0 = blockIdx.x * 32;
    const int tx = threadIdx.x, ty = threadIdx.y;
    float acc = 0.f;
    for (int k0 = 0; k0 < DM; k0 += 32) {
        Xs[ty][tx] = X[(size_t)(n0 + ty) * DM + k0 + tx];
        Ws[ty][tx] = W[(size_t)(j0 + ty) * DM + k0 + tx];
        __syncthreads();
#pragma unroll
        for (int kk = 0; kk < 32; kk++) acc += Xs[ty][kk] * Ws[tx][kk];
        __syncthreads();
    }
    if (which == 2) {
        __syncthreads();
        Xs[ty][tx] = acc;
        __syncthreads();
        float v = Xs[tx][ty];
        g_VT[(size_t)(j0 + ty) * NN + n0 + tx] = __float2half(v);
    } else {
        const size_t o = (size_t)(n0 + ty) * DM + j0 + tx;
        __half hi = __float2half(acc);
        __half lo = __float2half(acc - __half2float(hi));
        if (which == 0) { g_Qh[o] = hi; g_Ql[o] = lo; }
        else            { g_Kh[o] = hi; g_Kl[o] = lo; }
    }
}

// ---------------- kernel 3: P = relu(Q K^T) via HMMA -> u16 quantized planes ----------------
#define QK_ROWB 80
#define QK_ARR (128 * QK_ROWB)   // 10240

__global__ void __launch_bounds__(256, 2) k_qk_mma() {
    __shared__ char qsm[4 * QK_ARR];   // Qh, Ql, Kh, Kl
    const uint32_t sb = smem_u32(qsm);
    const int tid = threadIdx.x;
    const int wid = tid >> 5, lane = tid & 31;
    const int h = blockIdx.z;
    const int m0 = blockIdx.x * 128;   // key tile
    const int n0 = blockIdx.y * 128;   // query tile

    {
        const int r0 = tid >> 2, c = tid & 3;
#pragma unroll
        for (int j = 0; j < 2; j++) {
            const int r = r0 + j * 64;
            const uint32_t so = (uint32_t)(r * QK_ROWB + c * 16);
            const size_t qo = (size_t)(n0 + r) * DM + h * DH + c * 8;
            const size_t ko = (size_t)(m0 + r) * DM + h * DH + c * 8;
            cp16(sb + 0 * QK_ARR + so, g_Qh + qo);
            cp16(sb + 1 * QK_ARR + so, g_Ql + qo);
            cp16(sb + 2 * QK_ARR + so, g_Kh + ko);
            cp16(sb + 3 * QK_ARR + so, g_Kl + ko);
        }
    }
    asm volatile("cp.async.commit_group;" ::: "memory");
    asm volatile("cp.async.wait_group 0;" ::: "memory");
    __syncthreads();

    const int wm = wid & 1, wn = wid >> 1;
    float acc[4][4][4];
#pragma unroll
    for (int mi = 0; mi < 4; mi++)
#pragma unroll
        for (int ni = 0; ni < 4; ni++)
#pragma unroll
            for (int q = 0; q < 4; q++) acc[mi][ni][q] = 0.f;

    const int sel = lane >> 3, l7 = lane & 7;
    const int a_row = wm * 64 + (sel & 1) * 8 + l7;
    const int a_colb = (sel >> 1) * 16;
    const int b_row_base = wn * 32 + (sel >> 1) * 8 + l7;
    const int b_colb = (sel & 1) * 16;

#pragma unroll
    for (int ks = 0; ks < 2; ks++) {
        const int kb = ks * 32;
        uint32_t ahi[4][4], alo[4][4];
#pragma unroll
        for (int mi = 0; mi < 4; mi++) {
            const uint32_t ao = (uint32_t)((a_row + mi * 16) * QK_ROWB + kb + a_colb);
            ldsm_x4(ahi[mi], sb + 0 * QK_ARR + ao);
            ldsm_x4(alo[mi], sb + 1 * QK_ARR + ao);
        }
        uint32_t bhi[4][2], blo[4][2];
#pragma unroll
        for (int nb = 0; nb < 2; nb++) {
            const uint32_t bo = (uint32_t)((b_row_base + nb * 16) * QK_ROWB + kb + b_colb);
            uint32_t t[4];
            ldsm_x4(t, sb + 2 * QK_ARR + bo);
            bhi[2 * nb][0] = t[0]; bhi[2 * nb][1] = t[1];
            bhi[2 * nb + 1][0] = t[2]; bhi[2 * nb + 1][1] = t[3];
            ldsm_x4(t, sb + 3 * QK_ARR + bo);
            blo[2 * nb][0] = t[0]; blo[2 * nb][1] = t[1];
            blo[2 * nb + 1][0] = t[2]; blo[2 * nb + 1][1] = t[3];
        }
#pragma unroll
        for (int mi = 0; mi < 4; mi++)
#pragma unroll
            for (int ni = 0; ni < 4; ni++) mma16816(acc[mi][ni], ahi[mi], bhi[ni]);
#pragma unroll
        for (int mi = 0; mi < 4; mi++)
#pragma unroll
            for (int ni = 0; ni < 4; ni++) mma16816(acc[mi][ni], ahi[mi], blo[ni]);
#pragma unroll
        for (int mi = 0; mi < 4; mi++)
#pragma unroll
            for (int ni = 0; ni < 4; ni++) mma16816(acc[mi][ni], alo[mi], bhi[ni]);
    }

    const float qs = 65535.0f / PRANGE;
    const int er = lane >> 2, ec = (lane & 3) * 2;
#pragma unroll
    for (int mi = 0; mi < 4; mi++) {
#pragma unroll
        for (int ni = 0; ni < 4; ni++) {
            const int n = n0 + wm * 64 + mi * 16 + er;
            const int m = m0 + wn * 32 + ni * 8 + ec;
#pragma unroll
            for (int half = 0; half < 2; half++) {
                float p0 = fmaxf(acc[mi][ni][2 * half + 0], 0.f);
                float p1 = fmaxf(acc[mi][ni][2 * half + 1], 0.f);
                unsigned q0 = (unsigned)fminf(rintf(p0 * qs), 65535.0f);
                unsigned q1 = (unsigned)fminf(rintf(p1 * qs), 65535.0f);
                const size_t o = ((size_t)h * NN + n + half * 8) * NN + m;
                uchar2 hi2; hi2.x = (unsigned char)(q0 >> 8); hi2.y = (unsigned char)(q1 >> 8);
                uchar2 lo2; lo2.x = (unsigned char)(q0 & 255u); lo2.y = (unsigned char)(q1 & 255u);
                *(uchar2*)(g_Pq_hi + o) = hi2;
                *(uchar2*)(g_Pq_lo + o) = lo2;
            }
        }
    }
}

// ---------------- kernel 3b: rowsum of P16 (for the R = 1 + R' rank-1 term) ----------------
__global__ void __launch_bounds__(256) k_rowsum() {
    const size_t row = blockIdx.x;   // 0..NH*NN-1
    const int tid = threadIdx.x;
    const uint4* ph = (const uint4*)(g_Pq_hi + row * (size_t)NN);
    const uint4* pl = (const uint4*)(g_Pq_lo + row * (size_t)NN);
    uint4 hv = ph[tid], lv = pl[tid];
    unsigned sh = 0, sl = 0;
    sh = __dp4a(hv.x, 0x01010101u, sh); sh = __dp4a(hv.y, 0x01010101u, sh);
    sh = __dp4a(hv.z, 0x01010101u, sh); sh = __dp4a(hv.w, 0x01010101u, sh);
    sl = __dp4a(lv.x, 0x01010101u, sl); sl = __dp4a(lv.y, 0x01010101u, sl);
    sl = __dp4a(lv.z, 0x01010101u, sl); sl = __dp4a(lv.w, 0x01010101u, sl);
    int s = (int)((sh << 8) + sl);
#pragma unroll
    for (int o = 16; o; o >>= 1) s += __shfl_xor_sync(0xffffffffu, s, o);
    __shared__ int red[8];
    if ((tid & 31) == 0) red[tid >> 5] = s;
    __syncthreads();
    if (tid == 0) {
        int tot = 0;
#pragma unroll
        for (int i = 0; i < 8; i++) tot += red[i];
        g_S1[row] = tot;
    }
}

// ---------------- kernel 4: big GEMM, IMMA u8 split fixed-point ----------------
// CTA tile 128(M) x 128(N), K-chunk 128 (bytes = elems), 3-stage cp.async, 512 threads.
// S_int = 65536*acc0 + 256*acc12 (lo*lo dropped; rank-1 rowsum added in epilogue).
#define ROWB 144
#define PLANE (128 * ROWB)       // 18432
#define STAGE (4 * PLANE)        // 73728 (Phi, Plo, Rhi, Rlo)
#define GEMM_SMEM (3 * STAGE)    // 221184
#define KITERS (NN / 128)        // 32

__global__ void __launch_bounds__(512, 1) k_gemm() {
    extern __shared__ char smem[];
    const uint32_t sb = smem_u32(smem);
    const int tid = threadIdx.x;
    const int wid = tid >> 5, lane = tid & 31;
    const int h = blockIdx.y;

    // swizzle: 8x8 CTA groups (L2 locality)
    const int bid = blockIdx.x;          // 0..1023
    const int g = bid >> 6;              // 0..15
    const int gx = g & 3, gy = g >> 2;
    const int ny = gy * 8 + (bid & 7);          // m-tile (128 rows)
    const int nx = gx * 8 + ((bid >> 3) & 7);   // n-tile (128 cols)
    const int m0 = ny * 128, n0 = nx * 128;

    const unsigned char* __restrict__ Ahi = g_Pq_hi + ((size_t)h * NN + m0) * NN;
    const unsigned char* __restrict__ Alo = g_Pq_lo + ((size_t)h * NN + m0) * NN;
    const unsigned char* __restrict__ Bhi = g_Rq_hi + (size_t)n0 * NN;
    const unsigned char* __restrict__ Blo = g_Rq_lo + (size_t)n0 * NN;

    const int rl = tid >> 3, cl = tid & 7;   // 64 rows x 8 x 16B per pass

    auto issue_stage = [&](int it) {
        if (it < KITERS) {
            const uint32_t s0 = sb + (it % 3) * STAGE;
            const int kc = it * 128;
#pragma unroll
            for (int i = 0; i < 2; i++) {
                const int r = rl + i * 64;
                const uint32_t so = (uint32_t)(r * ROWB + cl * 16);
                const size_t go = (size_t)r * NN + kc + cl * 16;
                cp16(s0 + 0 * PLANE + so, Ahi + go);
                cp16(s0 + 1 * PLANE + so, Alo + go);
                cp16(s0 + 2 * PLANE + so, Bhi + go);
                cp16(s0 + 3 * PLANE + so, Blo + go);
            }
        }
        asm volatile("cp.async.commit_group;" ::: "memory");
    };

    // warp layout: 4 (M) x 4 (N); warp tile 32 x 32
    const int wm = wid & 3, wn = wid >> 2;
    int acc0[2][4][4], acc12[2][4][4];
#pragma unroll
    for (int mi = 0; mi < 2; mi++)
#pragma unroll
        for (int ni = 0; ni < 4; ni++)
#pragma unroll
            for (int q = 0; q < 4; q++) { acc0[mi][ni][q] = 0; acc12[mi][ni][q] = 0; }

    const int sel = lane >> 3, l7 = lane & 7;
    const int a_row = wm * 32 + (sel & 1) * 8 + l7;
    const int a_colb = (sel >> 1) * 16;
    const int b_row_base = wn * 32 + (sel >> 1) * 8 + l7;
    const int b_colb = (sel & 1) * 16;

    issue_stage(0);
    issue_stage(1);

    for (int it = 0; it < KITERS; it++) {
        asm volatile("cp.async.wait_group 1;" ::: "memory");
        __syncthreads();
        issue_stage(it + 2);

        const uint32_t s0 = sb + (it % 3) * STAGE;

#pragma unroll
        for (int ks = 0; ks < 4; ks++) {   // four k32 steps within the 128-chunk
            const int kb = ks * 32;        // byte offset
            uint32_t ahi[2][4], alo[2][4];
#pragma unroll
            for (int mi = 0; mi < 2; mi++) {
                const uint32_t ao = (uint32_t)((a_row + mi * 16) * ROWB + kb + a_colb);
                ldsm_x4(ahi[mi], s0 + 0 * PLANE + ao);
                ldsm_x4(alo[mi], s0 + 1 * PLANE + ao);
            }
            uint32_t bhi[4][2], blo[4][2];
#pragma unroll
            for (int nb = 0; nb < 2; nb++) {
                const uint32_t bo = (uint32_t)((b_row_base + nb * 16) * ROWB + kb + b_colb);
                uint32_t t[4];
                ldsm_x4(t, s0 + 2 * PLANE + bo);
                bhi[2 * nb][0] = t[0]; bhi[2 * nb][1] = t[1];
                bhi[2 * nb + 1][0] = t[2]; bhi[2 * nb + 1][1] = t[3];
                ldsm_x4(t, s0 + 3 * PLANE + bo);
                blo[2 * nb][0] = t[0]; blo[2 * nb][1] = t[1];
                blo[2 * nb + 1][0] = t[2]; blo[2 * nb + 1][1] = t[3];
            }
#pragma unroll
            for (int mi = 0; mi < 2; mi++)
#pragma unroll
                for (int ni = 0; ni < 4; ni++) mma16832u8(acc0[mi][ni], ahi[mi], bhi[ni]);
#pragma unroll
            for (int mi = 0; mi < 2; mi++)
#pragma unroll
                for (int ni = 0; ni < 4; ni++) mma16832u8(acc12[mi][ni], ahi[mi], blo[ni]);
#pragma unroll
            for (int mi = 0; mi < 2; mi++)
#pragma unroll
                for (int ni = 0; ni < 4; ni++) mma16832u8(acc12[mi][ni], alo[mi], bhi[ni]);
        }
    }

    // epilogue: score = (SP*S1_row + SP*SR*(65536*acc0 + 256*acc12)) / sqrt(32)
    const float SP = PRANGE / 65535.0f;
    const float SPSR = SP * (RRANGE / 65535.0f);
    const float inv_s = 0.17677669529663687f;
    const int er = lane >> 2, ec = (lane & 3) * 2;
#pragma unroll
    for (int mi = 0; mi < 2; mi++) {
        const int row = m0 + wm * 32 + mi * 16 + er;
        const float base0 = SP * (float)g_S1[(size_t)h * NN + row];
        const float base1 = SP * (float)g_S1[(size_t)h * NN + row + 8];
#pragma unroll
        for (int ni = 0; ni < 4; ni++) {
            const int col = n0 + wn * 32 + ni * 8 + ec;
            float2 v0, v1;
            v0.x = (base0 + SPSR * (65536.f * (float)acc0[mi][ni][0] + 256.f * (float)acc12[mi][ni][0])) * inv_s;
            v0.y = (base0 + SPSR * (65536.f * (float)acc0[mi][ni][1] + 256.f * (float)acc12[mi][ni][1])) * inv_s;
            v1.x = (base1 + SPSR * (65536.f * (float)acc0[mi][ni][2] + 256.f * (float)acc12[mi][ni][2])) * inv_s;
            v1.y = (base1 + SPSR * (65536.f * (float)acc0[mi][ni][3] + 256.f * (float)acc12[mi][ni][3])) * inv_s;
            *(float2*)(g_S + ((size_t)h * NN + row) * NN + col) = v0;
            *(float2*)(g_S + ((size_t)h * NN + row + 8) * NN + col) = v1;
        }
    }
}

// ---------------- kernel 5: softmax, warp-granular exp skip; fp16 attn out ----------------
__global__ void __launch_bounds__(256) k_softmax() {
    const size_t row = blockIdx.x;
    const float* p = g_S + row * (size_t)NN;
    __half* pa = g_Attn + row * (size_t)NN;
    const int tid = threadIdx.x;
    float x[16];
    float mx = -1e30f;
#pragma unroll
    for (int i = 0; i < 16; i++) { x[i] = p[tid + (i << 8)]; mx = fmaxf(mx, x[i]); }
    __shared__ float red[8];
#pragma unroll
    for (int o = 16; o; o >>= 1) mx = fmaxf(mx, __shfl_xor_sync(0xffffffffu, mx, o));
    if ((tid & 31) == 0) red[tid >> 5] = mx;
    __syncthreads();
    mx = red[0];
#pragma unroll
    for (int i = 1; i < 8; i++) mx = fmaxf(mx, red[i]);
    const float thr = mx - 20.0f;
    float s = 0.f;
#pragma unroll
    for (int i = 0; i < 16; i++) {
        if (__any_sync(0xffffffffu, x[i] >= thr)) {
            x[i] = (x[i] >= thr) ? __expf(x[i] - mx) : 0.f;
            s += x[i];
        } else {
            x[i] = 0.f;
        }
    }
#pragma unroll
    for (int o = 16; o; o >>= 1) s += __shfl_xor_sync(0xffffffffu, s, o);
    __syncthreads();
    if ((tid & 31) == 0) red[tid >> 5] = s;
    __syncthreads();
    s = ((red[0] + red[1]) + (red[2] + red[3])) + ((red[4] + red[5]) + (red[6] + red[7]));
    const float inv = 1.0f / s;
#pragma unroll
    for (int i = 0; i < 16; i++) pa[tid + (i << 8)] = __float2half(x[i] * inv);
}

// ---------------- kernel 6: out = attn @ V via HMMA ----------------
#define AV_ROWB 272
#define AV_A (64 * AV_ROWB)
#define AV_B (32 * AV_ROWB)
#define AV_STAGE (AV_A + AV_B)
#define AV_SMEM (2 * AV_STAGE)
#define AV_KITERS (NN / 128)

__global__ void __launch_bounds__(256) k_av(float* __restrict__ out) {
    extern __shared__ char avsm[];
    const uint32_t sb = smem_u32(avsm);
    const int tid = threadIdx.x;
    const int wid = tid >> 5, lane = tid & 31;
    const int h = blockIdx.y, n0 = blockIdx.x * 64;

    const __half* __restrict__ A = g_Attn + ((size_t)h * NN + n0) * NN;
    const __half* __restrict__ B = g_VT + (size_t)(h * DH) * NN;

    auto issue_stage = [&](int it) {
        if (it < AV_KITERS) {
            const uint32_t s0 = sb + (it & 1) * AV_STAGE;
            const int kc = it * 128;
#pragma unroll
            for (int i = 0; i < 4; i++) {
                const int idx = i * 256 + tid;
                const int r = idx >> 4, c = idx & 15;
                cp16(s0 + (uint32_t)(r * AV_ROWB + c * 16), A + (size_t)r * NN + kc + c * 8);
            }
#pragma unroll
            for (int i = 0; i < 2; i++) {
                const int idx = i * 256 + tid;
                const int r = idx >> 4, c = idx & 15;
                cp16(s0 + AV_A + (uint32_t)(r * AV_ROWB + c * 16), B + (size_t)r * NN + kc + c * 8);
            }
        }
        asm volatile("cp.async.commit_group;" ::: "memory");
    };

    const int wm = wid & 3, wn = wid >> 2;
    float acc[2][4];
#pragma unroll
    for (int ni = 0; ni < 2; ni++)
#pragma unroll
        for (int q = 0; q < 4; q++) acc[ni][q] = 0.f;

    const int sel = lane >> 3, l7 = lane & 7;
    const int a_row = wm * 16 + (sel & 1) * 8 + l7;
    const int a_colb = (sel >> 1) * 16;
    const int b_row = wn * 16 + (sel >> 1) * 8 + l7;
    const int b_colb = (sel & 1) * 16;

    issue_stage(0);

    for (int it = 0; it < AV_KITERS; it++) {
        asm volatile("cp.async.wait_group 0;" ::: "memory");
        __syncthreads();
        issue_stage(it + 1);

        const uint32_t s0 = sb + (it & 1) * AV_STAGE;
#pragma unroll
        for (int ks = 0; ks < 8; ks++) {
            const int kb = ks * 32;
            uint32_t a[4], b[4];
            ldsm_x4(a, s0 + (uint32_t)(a_row * AV_ROWB + kb + a_colb));
            ldsm_x4(b, s0 + AV_A + (uint32_t)(b_row * AV_ROWB + kb + b_colb));
            mma16816(acc[0], a, b + 0);
            mma16816(acc[1], a, b + 2);
        }
    }

    const int er = lane >> 2, ec = (lane & 3) * 2;
    const int n = n0 + wm * 16 + er;
#pragma unroll
    for (int ni = 0; ni < 2; ni++) {
        const int d = wn * 16 + ni * 8 + ec;
        *(float2*)(out + (size_t)n * DM + h * DH + d) = make_float2(acc[ni][0], acc[ni][1]);
        *(float2*)(out + (size_t)(n + 8) * DM + h * DH + d) = make_float2(acc[ni][2], acc[ni][3]);
    }
}

// ---------------- launch ----------------
extern "C" void kernel_launch(void* const* d_in, const int* in_sizes, int n_in,
                              void* d_out, int out_size) {
    (void)in_sizes; (void)n_in; (void)out_size;
    const float* Qin  = (const float*)d_in[0];
    const float* Kin  = (const float*)d_in[1];
    const float* Vin  = (const float*)d_in[2];
    // d_in[3] = adj_matrix: dead code in the reference
    const float* dist = (const float*)d_in[4];
    const float* WQ   = (const float*)d_in[5];
    const float* WK   = (const float*)d_in[6];
    const float* WV   = (const float*)d_in[7];
    float* out = (float*)d_out;

    k_rescale<<<dim3(128, 128), dim3(32, 32)>>>(dist);
    k_proj<<<dim3(8, 128), dim3(32, 32)>>>(Qin, WQ, 0);
    k_proj<<<dim3(8, 128), dim3(32, 32)>>>(Kin, WK, 1);
    k_proj<<<dim3(8, 128), dim3(32, 32)>>>(Vin, WV, 2);
    k_qk_mma<<<dim3(32, 32, 8), 256>>>();
    k_rowsum<<<dim3(NH * NN), 256>>>();

    cudaFuncSetAttribute(k_gemm, cudaFuncAttributeMaxDynamicSharedMemorySize, GEMM_SMEM);
    k_gemm<<<dim3(1024, 8), 512, GEMM_SMEM>>>();

    k_softmax<<<dim3(NH * NN), 256>>>();

    cudaFuncSetAttribute(k_av, cudaFuncAttributeMaxDynamicSharedMemorySize, AV_SMEM);
    k_av<<<dim3(64, 8), 256, AV_SMEM>>>(out);
}

// round 13
// speedup vs baseline: 2.7229x; 2.7229x over previous
#include <cuda_runtime.h>
#include <cuda_fp16.h>
#include <cstdint>
#include <cstddef>

#define NN 4096
#define DM 256
#define NH 8
#define DH 32

// ---------------- scratch (device globals; no allocation) ----------------
__device__ __half g_P_hi[(size_t)NH * NN * NN];   // relu(QK^T) hi split; REUSED as fp16 attn after softmax
__device__ __half g_P_lo[(size_t)NH * NN * NN];   // lo split
__device__ __half g_RT_hi[(size_t)NN * NN];       // rescale(dist)^T hi, [p][m]
__device__ __half g_RT_lo[(size_t)NN * NN];       // lo split
__device__ float  g_S[(size_t)NH * NN * NN];      // scores
__device__ __half g_Qh[(size_t)NN * DM];          // Q projection fp16 hi/lo
__device__ __half g_Ql[(size_t)NN * DM];
__device__ __half g_Kh[(size_t)NN * DM];
__device__ __half g_Kl[(size_t)NN * DM];
__device__ __half g_VT[(size_t)DM * NN];          // V^T fp16: g_VT[j][n] = V[n][j]

// ---------------- helpers ----------------
__device__ __forceinline__ uint32_t smem_u32(const void* p) {
    uint32_t a;
    asm("{ .reg .u64 t; cvta.to.shared.u64 t, %1; cvt.u32.u64 %0, t; }" : "=r"(a) : "l"(p));
    return a;
}

__device__ __forceinline__ void ldsm_x4(uint32_t* r, uint32_t addr) {
    asm volatile("ldmatrix.sync.aligned.m8n8.x4.shared.b16 {%0,%1,%2,%3}, [%4];"
                 : "=r"(r[0]), "=r"(r[1]), "=r"(r[2]), "=r"(r[3]) : "r"(addr));
}

__device__ __forceinline__ void mma16816(float* c, const uint32_t* a, const uint32_t* b) {
    asm volatile(
        "mma.sync.aligned.m16n8k16.row.col.f32.f16.f16.f32 "
        "{%0,%1,%2,%3}, {%4,%5,%6,%7}, {%8,%9}, {%0,%1,%2,%3};"
        : "+f"(c[0]), "+f"(c[1]), "+f"(c[2]), "+f"(c[3])
        : "r"(a[0]), "r"(a[1]), "r"(a[2]), "r"(a[3]), "r"(b[0]), "r"(b[1]));
}

__device__ __forceinline__ void cp16(uint32_t smem, const void* gmem) {
    asm volatile("cp.async.cg.shared.global [%0], [%1], 16;" :: "r"(smem), "l"(gmem));
}

// ---------------- kernel 1: R^T = rescale(dist)^T, fp16 split ----------------
__global__ void __launch_bounds__(1024) k_rescale(const float* __restrict__ dist) {
    __shared__ float t[32][33];
    const int m0 = blockIdx.y * 32, p0 = blockIdx.x * 32;
    const int tx = threadIdx.x, ty = threadIdx.y;
    float d = dist[(size_t)(m0 + ty) * NN + p0 + tx];
    t[ty][tx] = 3.718281828459045f / (1.0f + __expf(1.0f - d));
    __syncthreads();
    float r = t[tx][ty];  // = R[m0+tx][p0+ty]
    __half hi = __float2half(r);
    float lo = r - __half2float(hi);
    size_t o = (size_t)(p0 + ty) * NN + m0 + tx;
    g_RT_hi[o] = hi;
    g_RT_lo[o] = __float2half(lo);
}

// ---------------- kernel 2: projections out[n][j] = sum_k X[n][k]*W[j][k] ----------------
// which: 0 -> Q (fp16 hi/lo), 1 -> K (fp16 hi/lo), 2 -> V^T (fp16, transposed store)
__global__ void __launch_bounds__(1024) k_proj(const float* __restrict__ X,
                                               const float* __restrict__ W, int which) {
    __shared__ float Xs[32][33], Ws[32][33];
    const int n0 = blockIdx.y * 32, j0 = blockIdx.x * 32;
    const int tx = threadIdx.x, ty = threadIdx.y;
    float acc = 0.f;
    for (int k0 = 0; k0 < DM; k0 += 32) {
        Xs[ty][tx] = X[(size_t)(n0 + ty) * DM + k0 + tx];
        Ws[ty][tx] = W[(size_t)(j0 + ty) * DM + k0 + tx];
        __syncthreads();
#pragma unroll
        for (int kk = 0; kk < 32; kk++) acc += Xs[ty][kk] * Ws[tx][kk];
        __syncthreads();
    }
    if (which == 2) {
        // transpose through smem so V^T stores are coalesced in n
        __syncthreads();
        Xs[ty][tx] = acc;               // [n-local][j-local]
        __syncthreads();
        float v = Xs[tx][ty];           // value at [n = n0+tx][j = j0+ty]
        g_VT[(size_t)(j0 + ty) * NN + n0 + tx] = __float2half(v);
    } else {
        const size_t o = (size_t)(n0 + ty) * DM + j0 + tx;
        __half hi = __float2half(acc);
        __half lo = __float2half(acc - __half2float(hi));
        if (which == 0) { g_Qh[o] = hi; g_Ql[o] = lo; }
        else            { g_Kh[o] = hi; g_Kl[o] = lo; }
    }
}

// ---------------- kernel 3: P = relu(Q K^T) via HMMA, split precision ----------------
#define QK_ROWB 80
#define QK_ARR (128 * QK_ROWB)   // 10240

__global__ void __launch_bounds__(256, 2) k_qk_mma() {
    __shared__ char qsm[4 * QK_ARR];   // Qh, Ql, Kh, Kl
    const uint32_t sb = smem_u32(qsm);
    const int tid = threadIdx.x;
    const int wid = tid >> 5, lane = tid & 31;
    const int h = blockIdx.z;
    const int m0 = blockIdx.x * 128;   // key tile
    const int n0 = blockIdx.y * 128;   // query tile

    {
        const int r0 = tid >> 2, c = tid & 3;
#pragma unroll
        for (int j = 0; j < 2; j++) {
            const int r = r0 + j * 64;
            const uint32_t so = (uint32_t)(r * QK_ROWB + c * 16);
            const size_t qo = (size_t)(n0 + r) * DM + h * DH + c * 8;
            const size_t ko = (size_t)(m0 + r) * DM + h * DH + c * 8;
            cp16(sb + 0 * QK_ARR + so, g_Qh + qo);
            cp16(sb + 1 * QK_ARR + so, g_Ql + qo);
            cp16(sb + 2 * QK_ARR + so, g_Kh + ko);
            cp16(sb + 3 * QK_ARR + so, g_Kl + ko);
        }
    }
    asm volatile("cp.async.commit_group;" ::: "memory");
    asm volatile("cp.async.wait_group 0;" ::: "memory");
    __syncthreads();

    const int wm = wid & 1, wn = wid >> 1;
    float acc[4][4][4];
#pragma unroll
    for (int mi = 0; mi < 4; mi++)
#pragma unroll
        for (int ni = 0; ni < 4; ni++)
#pragma unroll
            for (int q = 0; q < 4; q++) acc[mi][ni][q] = 0.f;

    const int sel = lane >> 3, l7 = lane & 7;
    const int a_row = wm * 64 + (sel & 1) * 8 + l7;
    const int a_colb = (sel >> 1) * 16;
    const int b_row_base = wn * 32 + (sel >> 1) * 8 + l7;
    const int b_colb = (sel & 1) * 16;

#pragma unroll
    for (int ks = 0; ks < 2; ks++) {
        const int kb = ks * 32;
        uint32_t ahi[4][4], alo[4][4];
#pragma unroll
        for (int mi = 0; mi < 4; mi++) {
            const uint32_t ao = (uint32_t)((a_row + mi * 16) * QK_ROWB + kb + a_colb);
            ldsm_x4(ahi[mi], sb + 0 * QK_ARR + ao);
            ldsm_x4(alo[mi], sb + 1 * QK_ARR + ao);
        }
        uint32_t bhi[4][2], blo[4][2];
#pragma unroll
        for (int nb = 0; nb < 2; nb++) {
            const uint32_t bo = (uint32_t)((b_row_base + nb * 16) * QK_ROWB + kb + b_colb);
            uint32_t t[4];
            ldsm_x4(t, sb + 2 * QK_ARR + bo);
            bhi[2 * nb][0] = t[0]; bhi[2 * nb][1] = t[1];
            bhi[2 * nb + 1][0] = t[2]; bhi[2 * nb + 1][1] = t[3];
            ldsm_x4(t, sb + 3 * QK_ARR + bo);
            blo[2 * nb][0] = t[0]; blo[2 * nb][1] = t[1];
            blo[2 * nb + 1][0] = t[2]; blo[2 * nb + 1][1] = t[3];
        }
#pragma unroll
        for (int mi = 0; mi < 4; mi++)
#pragma unroll
            for (int ni = 0; ni < 4; ni++) mma16816(acc[mi][ni], ahi[mi], bhi[ni]);
#pragma unroll
        for (int mi = 0; mi < 4; mi++)
#pragma unroll
            for (int ni = 0; ni < 4; ni++) mma16816(acc[mi][ni], ahi[mi], blo[ni]);
#pragma unroll
        for (int mi = 0; mi < 4; mi++)
#pragma unroll
            for (int ni = 0; ni < 4; ni++) mma16816(acc[mi][ni], alo[mi], bhi[ni]);
    }

    const int er = lane >> 2, ec = (lane & 3) * 2;
#pragma unroll
    for (int mi = 0; mi < 4; mi++) {
#pragma unroll
        for (int ni = 0; ni < 4; ni++) {
            const int n = n0 + wm * 64 + mi * 16 + er;
            const int m = m0 + wn * 32 + ni * 8 + ec;
#pragma unroll
            for (int half = 0; half < 2; half++) {
                float p0 = fmaxf(acc[mi][ni][2 * half + 0], 0.f);
                float p1 = fmaxf(acc[mi][ni][2 * half + 1], 0.f);
                __half h0 = __float2half(p0), h1 = __float2half(p1);
                __half l0 = __float2half(p0 - __half2float(h0));
                __half l1 = __float2half(p1 - __half2float(h1));
                const size_t o = ((size_t)h * NN + n + half * 8) * NN + m;
                *(__half2*)(g_P_hi + o) = __halves2half2(h0, h1);
                *(__half2*)(g_P_lo + o) = __halves2half2(l0, l1);
            }
        }
    }
}

// ---------------- kernel 4: big GEMM (HMMA, split precision) ----------------
// CTA tile 256(M) x 128(N), K-chunk 64, 2-stage cp.async, 512 threads, 1 CTA/SM.
// blo fragment load deferred past the first two MMA sweeps to cap live registers.
#define ROWB 144
#define A_ARR (256 * ROWB)               // 36864
#define B_ARR (128 * ROWB)               // 18432
#define STAGE_SZ (2 * A_ARR + 2 * B_ARR) // 110592
#define GEMM_SMEM (2 * STAGE_SZ)         // 221184
#define KITERS (NN / 64)                 // 64

__global__ void __launch_bounds__(512, 1) k_gemm() {
    extern __shared__ char smem[];
    const uint32_t sb = smem_u32(smem);
    const int tid = threadIdx.x;
    const int wid = tid >> 5, lane = tid & 31;
    const int h = blockIdx.y;

    // swizzle: groups of 8(m) x 16(n) CTAs -> 64MB working set, fits L2
    const int bid = blockIdx.x;          // 0..511
    const int g = bid >> 7;              // 0..3
    const int gx = g & 1, gy = g >> 1;
    const int ny = gy * 8 + (bid & 7);          // m-tile (256 rows)
    const int nx = gx * 16 + ((bid >> 3) & 15); // n-tile (128 cols)
    const int m0 = ny * 256, n0 = nx * 128;

    const __half* __restrict__ Ahi = g_P_hi + ((size_t)h * NN + m0) * NN;
    const __half* __restrict__ Alo = g_P_lo + ((size_t)h * NN + m0) * NN;
    const __half* __restrict__ Bhi = g_RT_hi + (size_t)n0 * NN;
    const __half* __restrict__ Blo = g_RT_lo + (size_t)n0 * NN;

    const int rl = tid >> 3, cl = tid & 7;   // loader: 64 rows x 8 chunks per pass

    auto issue_stage = [&](int it) {
        if (it < KITERS) {
            const uint32_t s0 = sb + (it & 1) * STAGE_SZ;
            const int kc = it * 64;
#pragma unroll
            for (int i = 0; i < 4; i++) {        // A: 256 rows
                const int r = rl + i * 64;
                const uint32_t so = (uint32_t)(r * ROWB + cl * 16);
                const size_t go = (size_t)r * NN + kc + cl * 8;
                cp16(s0 + 0 * A_ARR + so, Ahi + go);
                cp16(s0 + 1 * A_ARR + so, Alo + go);
            }
#pragma unroll
            for (int i = 0; i < 2; i++) {        // B: 128 rows
                const int r = rl + i * 64;
                const uint32_t so = (uint32_t)(r * ROWB + cl * 16);
                const size_t go = (size_t)r * NN + kc + cl * 8;
                cp16(s0 + 2 * A_ARR + 0 * B_ARR + so, Bhi + go);
                cp16(s0 + 2 * A_ARR + 1 * B_ARR + so, Blo + go);
            }
        }
        asm volatile("cp.async.commit_group;" ::: "memory");
    };

    // warp layout: 4 (M) x 4 (N); warp tile 64 (M) x 32 (N)
    const int wm = wid & 3, wn = wid >> 2;
    float acc[4][4][4];
#pragma unroll
    for (int mi = 0; mi < 4; mi++)
#pragma unroll
        for (int ni = 0; ni < 4; ni++)
#pragma unroll
            for (int q = 0; q < 4; q++) acc[mi][ni][q] = 0.f;

    const int sel = lane >> 3, l7 = lane & 7;
    const int a_row = wm * 64 + (sel & 1) * 8 + l7;
    const int a_colb = (sel >> 1) * 16;
    const int b_row_base = wn * 32 + (sel >> 1) * 8 + l7;
    const int b_colb = (sel & 1) * 16;

    issue_stage(0);

    for (int it = 0; it < KITERS; it++) {
        asm volatile("cp.async.wait_group 0;" ::: "memory");
        __syncthreads();            // all warps past previous compute; this stage visible
        issue_stage(it + 1);        // fill other buffer while computing this one

        const uint32_t s0 = sb + (it & 1) * STAGE_SZ;
        const uint32_t pAhi = s0, pAlo = s0 + A_ARR;
        const uint32_t pBhi = s0 + 2 * A_ARR, pBlo = pBhi + B_ARR;

#pragma unroll
        for (int ks = 0; ks < 4; ks++) {   // four k16 steps within the 64-chunk
            const int kb = ks * 32;
            uint32_t ahi[4][4], alo[4][4];
#pragma unroll
            for (int mi = 0; mi < 4; mi++) {
                const uint32_t ao = (uint32_t)((a_row + mi * 16) * ROWB + kb + a_colb);
                ldsm_x4(ahi[mi], pAhi + ao);
                ldsm_x4(alo[mi], pAlo + ao);
            }
            uint32_t bhi[4][2];
#pragma unroll
            for (int nb = 0; nb < 2; nb++) {
                const uint32_t bo = (uint32_t)((b_row_base + nb * 16) * ROWB + kb + b_colb);
                uint32_t t[4];
                ldsm_x4(t, pBhi + bo);
                bhi[2 * nb][0] = t[0]; bhi[2 * nb][1] = t[1];
                bhi[2 * nb + 1][0] = t[2]; bhi[2 * nb + 1][1] = t[3];
            }
            // sweeps 1+2 use only {ahi, alo, bhi}
#pragma unroll
            for (int mi = 0; mi < 4; mi++)
#pragma unroll
                for (int ni = 0; ni < 4; ni++) mma16816(acc[mi][ni], ahi[mi], bhi[ni]);
#pragma unroll
            for (int mi = 0; mi < 4; mi++)
#pragma unroll
                for (int ni = 0; ni < 4; ni++) mma16816(acc[mi][ni], alo[mi], bhi[ni]);
            // blo loaded only now (alo + bhi registers free to be reused by ptxas)
            uint32_t blo[4][2];
#pragma unroll
            for (int nb = 0; nb < 2; nb++) {
                const uint32_t bo = (uint32_t)((b_row_base + nb * 16) * ROWB + kb + b_colb);
                uint32_t t[4];
                ldsm_x4(t, pBlo + bo);
                blo[2 * nb][0] = t[0]; blo[2 * nb][1] = t[1];
                blo[2 * nb + 1][0] = t[2]; blo[2 * nb + 1][1] = t[3];
            }
#pragma unroll
            for (int mi = 0; mi < 4; mi++)
#pragma unroll
                for (int ni = 0; ni < 4; ni++) mma16816(acc[mi][ni], ahi[mi], blo[ni]);
        }
    }

    // epilogue
    const float inv_s = 0.17677669529663687f;  // 1/sqrt(32)
    const int er = lane >> 2, ec = (lane & 3) * 2;
#pragma unroll
    for (int mi = 0; mi < 4; mi++) {
#pragma unroll
        for (int ni = 0; ni < 4; ni++) {
            const int col = n0 + wn * 32 + ni * 8 + ec;
            const int row = m0 + wm * 64 + mi * 16 + er;
            float2 v0 = make_float2(acc[mi][ni][0] * inv_s, acc[mi][ni][1] * inv_s);
            float2 v1 = make_float2(acc[mi][ni][2] * inv_s, acc[mi][ni][3] * inv_s);
            *(float2*)(g_S + ((size_t)h * NN + row) * NN + col) = v0;
            *(float2*)(g_S + ((size_t)h * NN + row + 8) * NN + col) = v1;
        }
    }
}

// ---------------- kernel 5: softmax, warp-granular exp skip; fp16 attn out ----------------
// Writes attn as fp16 into g_P_hi (P splits are dead after k_gemm).
__global__ void __launch_bounds__(256) k_softmax() {
    const size_t row = blockIdx.x;
    const float* p = g_S + row * (size_t)NN;
    __half* pa = g_P_hi + row * (size_t)NN;
    const int tid = threadIdx.x;
    float x[16];
    float mx = -1e30f;
#pragma unroll
    for (int i = 0; i < 16; i++) { x[i] = p[tid + (i << 8)]; mx = fmaxf(mx, x[i]); }
    __shared__ float red[8];
#pragma unroll
    for (int o = 16; o; o >>= 1) mx = fmaxf(mx, __shfl_xor_sync(0xffffffffu, mx, o));
    if ((tid & 31) == 0) red[tid >> 5] = mx;
    __syncthreads();
    mx = red[0];
#pragma unroll
    for (int i = 1; i < 8; i++) mx = fmaxf(mx, red[i]);
    const float thr = mx - 20.0f;
    float s = 0.f;
#pragma unroll
    for (int i = 0; i < 16; i++) {
        if (__any_sync(0xffffffffu, x[i] >= thr)) {
            x[i] = (x[i] >= thr) ? __expf(x[i] - mx) : 0.f;
            s += x[i];
        } else {
            x[i] = 0.f;
        }
    }
#pragma unroll
    for (int o = 16; o; o >>= 1) s += __shfl_xor_sync(0xffffffffu, s, o);
    __syncthreads();
    if ((tid & 31) == 0) red[tid >> 5] = s;
    __syncthreads();
    s = ((red[0] + red[1]) + (red[2] + red[3])) + ((red[4] + red[5]) + (red[6] + red[7]));
    const float inv = 1.0f / s;
#pragma unroll
    for (int i = 0; i < 16; i++) pa[tid + (i << 8)] = __float2half(x[i] * inv);
}

// ---------------- kernel 6: out = attn @ V via HMMA ----------------
// A = attn fp16 [64 x 4096] (g_P_hi), B = V^T fp16 [32 x 4096] (g_VT head slice).
#define AV_ROWB 272              // 256B data + 16B pad; bank base 4r mod 32, conflict-free
#define AV_A (64 * AV_ROWB)      // 17408
#define AV_B (32 * AV_ROWB)      // 8704
#define AV_STAGE (AV_A + AV_B)   // 26112
#define AV_SMEM (2 * AV_STAGE)   // 52224
#define AV_KITERS (NN / 128)     // 32

__global__ void __launch_bounds__(256) k_av(float* __restrict__ out) {
    extern __shared__ char avsm[];
    const uint32_t sb = smem_u32(avsm);
    const int tid = threadIdx.x;
    const int wid = tid >> 5, lane = tid & 31;
    const int h = blockIdx.y, n0 = blockIdx.x * 64;

    const __half* __restrict__ A = g_P_hi + ((size_t)h * NN + n0) * NN;   // attn rows
    const __half* __restrict__ B = g_VT + (size_t)(h * DH) * NN;          // V^T rows (d)

    auto issue_stage = [&](int it) {
        if (it < AV_KITERS) {
            const uint32_t s0 = sb + (it & 1) * AV_STAGE;
            const int kc = it * 128;
#pragma unroll
            for (int i = 0; i < 4; i++) {      // A: 64 rows x 16 chunks
                const int idx = i * 256 + tid;
                const int r = idx >> 4, c = idx & 15;
                cp16(s0 + (uint32_t)(r * AV_ROWB + c * 16), A + (size_t)r * NN + kc + c * 8);
            }
#pragma unroll
            for (int i = 0; i < 2; i++) {      // B: 32 rows x 16 chunks
                const int idx = i * 256 + tid;
                const int r = idx >> 4, c = idx & 15;
                cp16(s0 + AV_A + (uint32_t)(r * AV_ROWB + c * 16), B + (size_t)r * NN + kc + c * 8);
            }
        }
        asm volatile("cp.async.commit_group;" ::: "memory");
    };

    // warp layout: 4 (n-tiles of 16) x 2 (d-tiles of 16)
    const int wm = wid & 3, wn = wid >> 2;
    float acc[2][4];
#pragma unroll
    for (int ni = 0; ni < 2; ni++)
#pragma unroll
        for (int q = 0; q < 4; q++) acc[ni][q] = 0.f;

    const int sel = lane >> 3, l7 = lane & 7;
    const int a_row = wm * 16 + (sel & 1) * 8 + l7;
    const int a_colb = (sel >> 1) * 16;
    const int b_row = wn * 16 + (sel >> 1) * 8 + l7;
    const int b_colb = (sel & 1) * 16;

    issue_stage(0);

    for (int it = 0; it < AV_KITERS; it++) {
        asm volatile("cp.async.wait_group 0;" ::: "memory");
        __syncthreads();
        issue_stage(it + 1);

        const uint32_t s0 = sb + (it & 1) * AV_STAGE;
#pragma unroll
        for (int ks = 0; ks < 8; ks++) {
            const int kb = ks * 32;
            uint32_t a[4], b[4];
            ldsm_x4(a, s0 + (uint32_t)(a_row * AV_ROWB + kb + a_colb));
            ldsm_x4(b, s0 + AV_A + (uint32_t)(b_row * AV_ROWB + kb + b_colb));
            mma16816(acc[0], a, b + 0);
            mma16816(acc[1], a, b + 2);
        }
    }

    const int er = lane >> 2, ec = (lane & 3) * 2;
    const int n = n0 + wm * 16 + er;
#pragma unroll
    for (int ni = 0; ni < 2; ni++) {
        const int d = wn * 16 + ni * 8 + ec;
        *(float2*)(out + (size_t)n * DM + h * DH + d) = make_float2(acc[ni][0], acc[ni][1]);
        *(float2*)(out + (size_t)(n + 8) * DM + h * DH + d) = make_float2(acc[ni][2], acc[ni][3]);
    }
}

// ---------------- launch ----------------
extern "C" void kernel_launch(void* const* d_in, const int* in_sizes, int n_in,
                              void* d_out, int out_size) {
    (void)in_sizes; (void)n_in; (void)out_size;
    const float* Qin  = (const float*)d_in[0];
    const float* Kin  = (const float*)d_in[1];
    const float* Vin  = (const float*)d_in[2];
    // d_in[3] = adj_matrix: dead code in the reference
    const float* dist = (const float*)d_in[4];
    const float* WQ   = (const float*)d_in[5];
    const float* WK   = (const float*)d_in[6];
    const float* WV   = (const float*)d_in[7];
    float* out = (float*)d_out;

    k_rescale<<<dim3(128, 128), dim3(32, 32)>>>(dist);
    k_proj<<<dim3(8, 128), dim3(32, 32)>>>(Qin, WQ, 0);
    k_proj<<<dim3(8, 128), dim3(32, 32)>>>(Kin, WK, 1);
    k_proj<<<dim3(8, 128), dim3(32, 32)>>>(Vin, WV, 2);
    k_qk_mma<<<dim3(32, 32, 8), 256>>>();

    cudaFuncSetAttribute(k_gemm, cudaFuncAttributeMaxDynamicSharedMemorySize, GEMM_SMEM);
    k_gemm<<<dim3(512, 8), 512, GEMM_SMEM>>>();

    k_softmax<<<dim3(NH * NN), 256>>>();

    cudaFuncSetAttribute(k_av, cudaFuncAttributeMaxDynamicSharedMemorySize, AV_SMEM);
    k_av<<<dim3(64, 8), 256, AV_SMEM>>>(out);
}

// round 14
// speedup vs baseline: 2.8342x; 1.0409x over previous
#include <cuda_runtime.h>
#include <cuda_fp16.h>
#include <cstdint>
#include <cstddef>

#define NN 4096
#define DM 256
#define NH 8
#define DH 32

// ---------------- scratch (device globals; no allocation) ----------------
__device__ __half g_P_hi[(size_t)NH * NN * NN];   // relu(QK^T) hi split; REUSED as fp16 attn after softmax
__device__ __half g_P_lo[(size_t)NH * NN * NN];   // lo split
__device__ __half g_RT_hi[(size_t)NN * NN];       // rescale(dist)^T hi, [p][m]
__device__ __half g_RT_lo[(size_t)NN * NN];       // lo split
__device__ float  g_S[(size_t)NH * NN * NN];      // scores
__device__ __half g_Qh[(size_t)NN * DM];          // Q projection fp16 hi/lo
__device__ __half g_Ql[(size_t)NN * DM];
__device__ __half g_Kh[(size_t)NN * DM];
__device__ __half g_Kl[(size_t)NN * DM];
__device__ __half g_VT[(size_t)DM * NN];          // V^T fp16: g_VT[j][n] = V[n][j]

// ---------------- helpers ----------------
__device__ __forceinline__ uint32_t smem_u32(const void* p) {
    uint32_t a;
    asm("{ .reg .u64 t; cvta.to.shared.u64 t, %1; cvt.u32.u64 %0, t; }" : "=r"(a) : "l"(p));
    return a;
}

__device__ __forceinline__ void ldsm_x4(uint32_t* r, uint32_t addr) {
    asm volatile("ldmatrix.sync.aligned.m8n8.x4.shared.b16 {%0,%1,%2,%3}, [%4];"
                 : "=r"(r[0]), "=r"(r[1]), "=r"(r[2]), "=r"(r[3]) : "r"(addr));
}

__device__ __forceinline__ void mma16816(float* c, const uint32_t* a, const uint32_t* b) {
    asm volatile(
        "mma.sync.aligned.m16n8k16.row.col.f32.f16.f16.f32 "
        "{%0,%1,%2,%3}, {%4,%5,%6,%7}, {%8,%9}, {%0,%1,%2,%3};"
        : "+f"(c[0]), "+f"(c[1]), "+f"(c[2]), "+f"(c[3])
        : "r"(a[0]), "r"(a[1]), "r"(a[2]), "r"(a[3]), "r"(b[0]), "r"(b[1]));
}

__device__ __forceinline__ void cp16(uint32_t smem, const void* gmem) {
    asm volatile("cp.async.cg.shared.global [%0], [%1], 16;" :: "r"(smem), "l"(gmem));
}

// ---------------- kernel 1: R^T = rescale(dist)^T, fp16 split ----------------
__global__ void __launch_bounds__(1024) k_rescale(const float* __restrict__ dist) {
    __shared__ float t[32][33];
    const int m0 = blockIdx.y * 32, p0 = blockIdx.x * 32;
    const int tx = threadIdx.x, ty = threadIdx.y;
    float d = dist[(size_t)(m0 + ty) * NN + p0 + tx];
    t[ty][tx] = 3.718281828459045f / (1.0f + __expf(1.0f - d));
    __syncthreads();
    float r = t[tx][ty];  // = R[m0+tx][p0+ty]
    __half hi = __float2half(r);
    float lo = r - __half2float(hi);
    size_t o = (size_t)(p0 + ty) * NN + m0 + tx;
    g_RT_hi[o] = hi;
    g_RT_lo[o] = __float2half(lo);
}

// ---------------- kernel 2a: Q/K projections, tiled 64x64, 4x4 microtile ----------------
// z=0 -> Q, z=1 -> K. out[n][j] = sum_k X[n][k]*W[j][k], split fp16 hi/lo.
__global__ void __launch_bounds__(256) k_projqk(const float* __restrict__ Qin,
                                                const float* __restrict__ Kin,
                                                const float* __restrict__ WQ,
                                                const float* __restrict__ WK) {
    const float* __restrict__ X = blockIdx.z ? Kin : Qin;
    const float* __restrict__ W = blockIdx.z ? WK : WQ;
    __half* Oh = blockIdx.z ? g_Kh : g_Qh;
    __half* Ol = blockIdx.z ? g_Kl : g_Ql;

    __shared__ float Xs[32][68];   // [k][n], row stride 68 (16B-aligned rows)
    __shared__ float Ws[32][68];   // [k][j]
    const int j0g = blockIdx.x * 64, n0g = blockIdx.y * 64;
    const int tid = threadIdx.x;
    const int jt = (tid & 15) * 4;   // 4 consecutive j
    const int nt = (tid >> 4) * 4;   // 4 consecutive n
    const int lr = tid >> 2;         // loader row 0..63
    const int lc = (tid & 3) * 8;    // loader k offset

    float acc[4][4];
#pragma unroll
    for (int a = 0; a < 4; a++)
#pragma unroll
        for (int b = 0; b < 4; b++) acc[a][b] = 0.f;

    for (int k0 = 0; k0 < DM; k0 += 32) {
        __syncthreads();
        float4 a0 = *(const float4*)&X[(size_t)(n0g + lr) * DM + k0 + lc];
        float4 a1 = *(const float4*)&X[(size_t)(n0g + lr) * DM + k0 + lc + 4];
        Xs[lc + 0][lr] = a0.x; Xs[lc + 1][lr] = a0.y; Xs[lc + 2][lr] = a0.z; Xs[lc + 3][lr] = a0.w;
        Xs[lc + 4][lr] = a1.x; Xs[lc + 5][lr] = a1.y; Xs[lc + 6][lr] = a1.z; Xs[lc + 7][lr] = a1.w;
        float4 b0 = *(const float4*)&W[(size_t)(j0g + lr) * DM + k0 + lc];
        float4 b1 = *(const float4*)&W[(size_t)(j0g + lr) * DM + k0 + lc + 4];
        Ws[lc + 0][lr] = b0.x; Ws[lc + 1][lr] = b0.y; Ws[lc + 2][lr] = b0.z; Ws[lc + 3][lr] = b0.w;
        Ws[lc + 4][lr] = b1.x; Ws[lc + 5][lr] = b1.y; Ws[lc + 6][lr] = b1.z; Ws[lc + 7][lr] = b1.w;
        __syncthreads();
#pragma unroll
        for (int kk = 0; kk < 32; kk++) {
            float4 xv = *(const float4*)&Xs[kk][nt];
            float4 wv = *(const float4*)&Ws[kk][jt];
            const float xr[4] = {xv.x, xv.y, xv.z, xv.w};
            const float wr[4] = {wv.x, wv.y, wv.z, wv.w};
#pragma unroll
            for (int a = 0; a < 4; a++)
#pragma unroll
                for (int b = 0; b < 4; b++) acc[a][b] += xr[a] * wr[b];
        }
    }

#pragma unroll
    for (int a = 0; a < 4; a++) {
        const int n = n0g + nt + a;
        __half h[4], l[4];
#pragma unroll
        for (int b = 0; b < 4; b++) {
            h[b] = __float2half(acc[a][b]);
            l[b] = __float2half(acc[a][b] - __half2float(h[b]));
        }
        const size_t o = (size_t)n * DM + j0g + jt;
        *(__half2*)&Oh[o] = __halves2half2(h[0], h[1]);
        *(__half2*)&Oh[o + 2] = __halves2half2(h[2], h[3]);
        *(__half2*)&Ol[o] = __halves2half2(l[0], l[1]);
        *(__half2*)&Ol[o + 2] = __halves2half2(l[2], l[3]);
    }
}

// ---------------- kernel 2b: V projection (transposed fp16 out) ----------------
__global__ void __launch_bounds__(1024) k_projv(const float* __restrict__ X,
                                                const float* __restrict__ W) {
    __shared__ float Xs[32][33], Ws[32][33];
    const int n0 = blockIdx.y * 32, j0 = blockIdx.x * 32;
    const int tx = threadIdx.x, ty = threadIdx.y;
    float acc = 0.f;
    for (int k0 = 0; k0 < DM; k0 += 32) {
        Xs[ty][tx] = X[(size_t)(n0 + ty) * DM + k0 + tx];
        Ws[ty][tx] = W[(size_t)(j0 + ty) * DM + k0 + tx];
        __syncthreads();
#pragma unroll
        for (int kk = 0; kk < 32; kk++) acc += Xs[ty][kk] * Ws[tx][kk];
        __syncthreads();
    }
    // transpose through smem so V^T stores are coalesced in n
    __syncthreads();
    Xs[ty][tx] = acc;               // [n-local][j-local]
    __syncthreads();
    float v = Xs[tx][ty];           // value at [n = n0+tx][j = j0+ty]
    g_VT[(size_t)(j0 + ty) * NN + n0 + tx] = __float2half(v);
}

// ---------------- kernel 3: P = relu(Q K^T) via HMMA, split precision ----------------
#define QK_ROWB 80
#define QK_ARR (128 * QK_ROWB)   // 10240

__global__ void __launch_bounds__(256, 2) k_qk_mma() {
    __shared__ char qsm[4 * QK_ARR];   // Qh, Ql, Kh, Kl
    const uint32_t sb = smem_u32(qsm);
    const int tid = threadIdx.x;
    const int wid = tid >> 5, lane = tid & 31;
    const int h = blockIdx.z;
    const int m0 = blockIdx.x * 128;   // key tile
    const int n0 = blockIdx.y * 128;   // query tile

    {
        const int r0 = tid >> 2, c = tid & 3;
#pragma unroll
        for (int j = 0; j < 2; j++) {
            const int r = r0 + j * 64;
            const uint32_t so = (uint32_t)(r * QK_ROWB + c * 16);
            const size_t qo = (size_t)(n0 + r) * DM + h * DH + c * 8;
            const size_t ko = (size_t)(m0 + r) * DM + h * DH + c * 8;
            cp16(sb + 0 * QK_ARR + so, g_Qh + qo);
            cp16(sb + 1 * QK_ARR + so, g_Ql + qo);
            cp16(sb + 2 * QK_ARR + so, g_Kh + ko);
            cp16(sb + 3 * QK_ARR + so, g_Kl + ko);
        }
    }
    asm volatile("cp.async.commit_group;" ::: "memory");
    asm volatile("cp.async.wait_group 0;" ::: "memory");
    __syncthreads();

    const int wm = wid & 1, wn = wid >> 1;
    float acc[4][4][4];
#pragma unroll
    for (int mi = 0; mi < 4; mi++)
#pragma unroll
        for (int ni = 0; ni < 4; ni++)
#pragma unroll
            for (int q = 0; q < 4; q++) acc[mi][ni][q] = 0.f;

    const int sel = lane >> 3, l7 = lane & 7;
    const int a_row = wm * 64 + (sel & 1) * 8 + l7;
    const int a_colb = (sel >> 1) * 16;
    const int b_row_base = wn * 32 + (sel >> 1) * 8 + l7;
    const int b_colb = (sel & 1) * 16;

#pragma unroll
    for (int ks = 0; ks < 2; ks++) {
        const int kb = ks * 32;
        uint32_t ahi[4][4], alo[4][4];
#pragma unroll
        for (int mi = 0; mi < 4; mi++) {
            const uint32_t ao = (uint32_t)((a_row + mi * 16) * QK_ROWB + kb + a_colb);
            ldsm_x4(ahi[mi], sb + 0 * QK_ARR + ao);
            ldsm_x4(alo[mi], sb + 1 * QK_ARR + ao);
        }
        uint32_t bhi[4][2], blo[4][2];
#pragma unroll
        for (int nb = 0; nb < 2; nb++) {
            const uint32_t bo = (uint32_t)((b_row_base + nb * 16) * QK_ROWB + kb + b_colb);
            uint32_t t[4];
            ldsm_x4(t, sb + 2 * QK_ARR + bo);
            bhi[2 * nb][0] = t[0]; bhi[2 * nb][1] = t[1];
            bhi[2 * nb + 1][0] = t[2]; bhi[2 * nb + 1][1] = t[3];
            ldsm_x4(t, sb + 3 * QK_ARR + bo);
            blo[2 * nb][0] = t[0]; blo[2 * nb][1] = t[1];
            blo[2 * nb + 1][0] = t[2]; blo[2 * nb + 1][1] = t[3];
        }
#pragma unroll
        for (int mi = 0; mi < 4; mi++)
#pragma unroll
            for (int ni = 0; ni < 4; ni++) mma16816(acc[mi][ni], ahi[mi], bhi[ni]);
#pragma unroll
        for (int mi = 0; mi < 4; mi++)
#pragma unroll
            for (int ni = 0; ni < 4; ni++) mma16816(acc[mi][ni], ahi[mi], blo[ni]);
#pragma unroll
        for (int mi = 0; mi < 4; mi++)
#pragma unroll
            for (int ni = 0; ni < 4; ni++) mma16816(acc[mi][ni], alo[mi], bhi[ni]);
    }

    const int er = lane >> 2, ec = (lane & 3) * 2;
#pragma unroll
    for (int mi = 0; mi < 4; mi++) {
#pragma unroll
        for (int ni = 0; ni < 4; ni++) {
            const int n = n0 + wm * 64 + mi * 16 + er;
            const int m = m0 + wn * 32 + ni * 8 + ec;
#pragma unroll
            for (int half = 0; half < 2; half++) {
                float p0 = fmaxf(acc[mi][ni][2 * half + 0], 0.f);
                float p1 = fmaxf(acc[mi][ni][2 * half + 1], 0.f);
                __half h0 = __float2half(p0), h1 = __float2half(p1);
                __half l0 = __float2half(p0 - __half2float(h0));
                __half l1 = __float2half(p1 - __half2float(h1));
                const size_t o = ((size_t)h * NN + n + half * 8) * NN + m;
                *(__half2*)(g_P_hi + o) = __halves2half2(h0, h1);
                *(__half2*)(g_P_lo + o) = __halves2half2(l0, l1);
            }
        }
    }
}

// ---------------- kernel 4: big GEMM (HMMA, split precision) ----------------
// CTA tile 256(M) x 128(N), K-chunk 64, 2-stage cp.async, 512 threads, 1 CTA/SM.
#define ROWB 144
#define A_ARR (256 * ROWB)               // 36864
#define B_ARR (128 * ROWB)               // 18432
#define STAGE_SZ (2 * A_ARR + 2 * B_ARR) // 110592
#define GEMM_SMEM (2 * STAGE_SZ)         // 221184
#define KITERS (NN / 64)                 // 64

__global__ void __launch_bounds__(512, 1) k_gemm() {
    extern __shared__ char smem[];
    const uint32_t sb = smem_u32(smem);
    const int tid = threadIdx.x;
    const int wid = tid >> 5, lane = tid & 31;
    const int h = blockIdx.y;

    // swizzle: groups of 8(m) x 16(n) CTAs -> 64MB working set, fits L2
    const int bid = blockIdx.x;          // 0..511
    const int g = bid >> 7;              // 0..3
    const int gx = g & 1, gy = g >> 1;
    const int ny = gy * 8 + (bid & 7);          // m-tile (256 rows)
    const int nx = gx * 16 + ((bid >> 3) & 15); // n-tile (128 cols)
    const int m0 = ny * 256, n0 = nx * 128;

    const __half* __restrict__ Ahi = g_P_hi + ((size_t)h * NN + m0) * NN;
    const __half* __restrict__ Alo = g_P_lo + ((size_t)h * NN + m0) * NN;
    const __half* __restrict__ Bhi = g_RT_hi + (size_t)n0 * NN;
    const __half* __restrict__ Blo = g_RT_lo + (size_t)n0 * NN;

    const int rl = tid >> 3, cl = tid & 7;   // loader: 64 rows x 8 chunks per pass

    auto issue_stage = [&](int it) {
        if (it < KITERS) {
            const uint32_t s0 = sb + (it & 1) * STAGE_SZ;
            const int kc = it * 64;
#pragma unroll
            for (int i = 0; i < 4; i++) {        // A: 256 rows
                const int r = rl + i * 64;
                const uint32_t so = (uint32_t)(r * ROWB + cl * 16);
                const size_t go = (size_t)r * NN + kc + cl * 8;
                cp16(s0 + 0 * A_ARR + so, Ahi + go);
                cp16(s0 + 1 * A_ARR + so, Alo + go);
            }
#pragma unroll
            for (int i = 0; i < 2; i++) {        // B: 128 rows
                const int r = rl + i * 64;
                const uint32_t so = (uint32_t)(r * ROWB + cl * 16);
                const size_t go = (size_t)r * NN + kc + cl * 8;
                cp16(s0 + 2 * A_ARR + 0 * B_ARR + so, Bhi + go);
                cp16(s0 + 2 * A_ARR + 1 * B_ARR + so, Blo + go);
            }
        }
        asm volatile("cp.async.commit_group;" ::: "memory");
    };

    // warp layout: 4 (M) x 4 (N); warp tile 64 (M) x 32 (N)
    const int wm = wid & 3, wn = wid >> 2;
    float acc[4][4][4];
#pragma unroll
    for (int mi = 0; mi < 4; mi++)
#pragma unroll
        for (int ni = 0; ni < 4; ni++)
#pragma unroll
            for (int q = 0; q < 4; q++) acc[mi][ni][q] = 0.f;

    const int sel = lane >> 3, l7 = lane & 7;
    const int a_row = wm * 64 + (sel & 1) * 8 + l7;
    const int a_colb = (sel >> 1) * 16;
    const int b_row_base = wn * 32 + (sel >> 1) * 8 + l7;
    const int b_colb = (sel & 1) * 16;

    issue_stage(0);

    for (int it = 0; it < KITERS; it++) {
        asm volatile("cp.async.wait_group 0;" ::: "memory");
        __syncthreads();            // all warps past previous compute; this stage visible
        issue_stage(it + 1);        // fill other buffer while computing this one

        const uint32_t s0 = sb + (it & 1) * STAGE_SZ;
        const uint32_t pAhi = s0, pAlo = s0 + A_ARR;
        const uint32_t pBhi = s0 + 2 * A_ARR, pBlo = pBhi + B_ARR;

#pragma unroll
        for (int ks = 0; ks < 4; ks++) {   // four k16 steps within the 64-chunk
            const int kb = ks * 32;
            uint32_t ahi[4][4], alo[4][4];
#pragma unroll
            for (int mi = 0; mi < 4; mi++) {
                const uint32_t ao = (uint32_t)((a_row + mi * 16) * ROWB + kb + a_colb);
                ldsm_x4(ahi[mi], pAhi + ao);
                ldsm_x4(alo[mi], pAlo + ao);
            }
            uint32_t bhi[4][2], blo[4][2];
#pragma unroll
            for (int nb = 0; nb < 2; nb++) {
                const uint32_t bo = (uint32_t)((b_row_base + nb * 16) * ROWB + kb + b_colb);
                uint32_t t[4];
                ldsm_x4(t, pBhi + bo);
                bhi[2 * nb][0] = t[0]; bhi[2 * nb][1] = t[1];
                bhi[2 * nb + 1][0] = t[2]; bhi[2 * nb + 1][1] = t[3];
                ldsm_x4(t, pBlo + bo);
                blo[2 * nb][0] = t[0]; blo[2 * nb][1] = t[1];
                blo[2 * nb + 1][0] = t[2]; blo[2 * nb + 1][1] = t[3];
            }
#pragma unroll
            for (int mi = 0; mi < 4; mi++)
#pragma unroll
                for (int ni = 0; ni < 4; ni++) mma16816(acc[mi][ni], ahi[mi], bhi[ni]);
#pragma unroll
            for (int mi = 0; mi < 4; mi++)
#pragma unroll
                for (int ni = 0; ni < 4; ni++) mma16816(acc[mi][ni], ahi[mi], blo[ni]);
#pragma unroll
            for (int mi = 0; mi < 4; mi++)
#pragma unroll
                for (int ni = 0; ni < 4; ni++) mma16816(acc[mi][ni], alo[mi], bhi[ni]);
        }
    }

    // epilogue
    const float inv_s = 0.17677669529663687f;  // 1/sqrt(32)
    const int er = lane >> 2, ec = (lane & 3) * 2;
#pragma unroll
    for (int mi = 0; mi < 4; mi++) {
#pragma unroll
        for (int ni = 0; ni < 4; ni++) {
            const int col = n0 + wn * 32 + ni * 8 + ec;
            const int row = m0 + wm * 64 + mi * 16 + er;
            float2 v0 = make_float2(acc[mi][ni][0] * inv_s, acc[mi][ni][1] * inv_s);
            float2 v1 = make_float2(acc[mi][ni][2] * inv_s, acc[mi][ni][3] * inv_s);
            *(float2*)(g_S + ((size_t)h * NN + row) * NN + col) = v0;
            *(float2*)(g_S + ((size_t)h * NN + row + 8) * NN + col) = v1;
        }
    }
}

// ---------------- kernel 5: softmax, warp-granular exp skip; fp16 attn out ----------------
// Writes attn as fp16 into g_P_hi (P splits are dead after k_gemm).
__global__ void __launch_bounds__(256) k_softmax() {
    const size_t row = blockIdx.x;
    const float* p = g_S + row * (size_t)NN;
    __half* pa = g_P_hi + row * (size_t)NN;
    const int tid = threadIdx.x;
    float x[16];
    float mx = -1e30f;
#pragma unroll
    for (int i = 0; i < 16; i++) { x[i] = p[tid + (i << 8)]; mx = fmaxf(mx, x[i]); }
    __shared__ float red[8];
#pragma unroll
    for (int o = 16; o; o >>= 1) mx = fmaxf(mx, __shfl_xor_sync(0xffffffffu, mx, o));
    if ((tid & 31) == 0) red[tid >> 5] = mx;
    __syncthreads();
    mx = red[0];
#pragma unroll
    for (int i = 1; i < 8; i++) mx = fmaxf(mx, red[i]);
    const float thr = mx - 20.0f;
    float s = 0.f;
#pragma unroll
    for (int i = 0; i < 16; i++) {
        if (__any_sync(0xffffffffu, x[i] >= thr)) {
            x[i] = (x[i] >= thr) ? __expf(x[i] - mx) : 0.f;
            s += x[i];
        } else {
            x[i] = 0.f;
        }
    }
#pragma unroll
    for (int o = 16; o; o >>= 1) s += __shfl_xor_sync(0xffffffffu, s, o);
    __syncthreads();
    if ((tid & 31) == 0) red[tid >> 5] = s;
    __syncthreads();
    s = ((red[0] + red[1]) + (red[2] + red[3])) + ((red[4] + red[5]) + (red[6] + red[7]));
    const float inv = 1.0f / s;
#pragma unroll
    for (int i = 0; i < 16; i++) pa[tid + (i << 8)] = __float2half(x[i] * inv);
}

// ---------------- kernel 6: out = attn @ V via HMMA ----------------
// A = attn fp16 [64 x 4096] (g_P_hi), B = V^T fp16 [32 x 4096] (g_VT head slice).
#define AV_ROWB 272              // 256B data + 16B pad; bank base 4r mod 32, conflict-free
#define AV_A (64 * AV_ROWB)      // 17408
#define AV_B (32 * AV_ROWB)      // 8704
#define AV_STAGE (AV_A + AV_B)   // 26112
#define AV_SMEM (2 * AV_STAGE)   // 52224
#define AV_KITERS (NN / 128)     // 32

__global__ void __launch_bounds__(256) k_av(float* __restrict__ out) {
    extern __shared__ char avsm[];
    const uint32_t sb = smem_u32(avsm);
    const int tid = threadIdx.x;
    const int wid = tid >> 5, lane = tid & 31;
    const int h = blockIdx.y, n0 = blockIdx.x * 64;

    const __half* __restrict__ A = g_P_hi + ((size_t)h * NN + n0) * NN;   // attn rows
    const __half* __restrict__ B = g_VT + (size_t)(h * DH) * NN;          // V^T rows (d)

    auto issue_stage = [&](int it) {
        if (it < AV_KITERS) {
            const uint32_t s0 = sb + (it & 1) * AV_STAGE;
            const int kc = it * 128;
#pragma unroll
            for (int i = 0; i < 4; i++) {      // A: 64 rows x 16 chunks
                const int idx = i * 256 + tid;
                const int r = idx >> 4, c = idx & 15;
                cp16(s0 + (uint32_t)(r * AV_ROWB + c * 16), A + (size_t)r * NN + kc + c * 8);
            }
#pragma unroll
            for (int i = 0; i < 2; i++) {      // B: 32 rows x 16 chunks
                const int idx = i * 256 + tid;
                const int r = idx >> 4, c = idx & 15;
                cp16(s0 + AV_A + (uint32_t)(r * AV_ROWB + c * 16), B + (size_t)r * NN + kc + c * 8);
            }
        }
        asm volatile("cp.async.commit_group;" ::: "memory");
    };

    // warp layout: 4 (n-tiles of 16) x 2 (d-tiles of 16)
    const int wm = wid & 3, wn = wid >> 2;
    float acc[2][4];
#pragma unroll
    for (int ni = 0; ni < 2; ni++)
#pragma unroll
        for (int q = 0; q < 4; q++) acc[ni][q] = 0.f;

    const int sel = lane >> 3, l7 = lane & 7;
    const int a_row = wm * 16 + (sel & 1) * 8 + l7;
    const int a_colb = (sel >> 1) * 16;
    const int b_row = wn * 16 + (sel >> 1) * 8 + l7;
    const int b_colb = (sel & 1) * 16;

    issue_stage(0);

    for (int it = 0; it < AV_KITERS; it++) {
        asm volatile("cp.async.wait_group 0;" ::: "memory");
        __syncthreads();
        issue_stage(it + 1);

        const uint32_t s0 = sb + (it & 1) * AV_STAGE;
#pragma unroll
        for (int ks = 0; ks < 8; ks++) {
            const int kb = ks * 32;
            uint32_t a[4], b[4];
            ldsm_x4(a, s0 + (uint32_t)(a_row * AV_ROWB + kb + a_colb));
            ldsm_x4(b, s0 + AV_A + (uint32_t)(b_row * AV_ROWB + kb + b_colb));
            mma16816(acc[0], a, b + 0);
            mma16816(acc[1], a, b + 2);
        }
    }

    const int er = lane >> 2, ec = (lane & 3) * 2;
    const int n = n0 + wm * 16 + er;
#pragma unroll
    for (int ni = 0; ni < 2; ni++) {
        const int d = wn * 16 + ni * 8 + ec;
        *(float2*)(out + (size_t)n * DM + h * DH + d) = make_float2(acc[ni][0], acc[ni][1]);
        *(float2*)(out + (size_t)(n + 8) * DM + h * DH + d) = make_float2(acc[ni][2], acc[ni][3]);
    }
}

// ---------------- launch ----------------
extern "C" void kernel_launch(void* const* d_in, const int* in_sizes, int n_in,
                              void* d_out, int out_size) {
    (void)in_sizes; (void)n_in; (void)out_size;
    const float* Qin  = (const float*)d_in[0];
    const float* Kin  = (const float*)d_in[1];
    const float* Vin  = (const float*)d_in[2];
    // d_in[3] = adj_matrix: dead code in the reference
    const float* dist = (const float*)d_in[4];
    const float* WQ   = (const float*)d_in[5];
    const float* WK   = (const float*)d_in[6];
    const float* WV   = (const float*)d_in[7];
    float* out = (float*)d_out;

    k_rescale<<<dim3(128, 128), dim3(32, 32)>>>(dist);
    k_projqk<<<dim3(4, 64, 2), 256>>>(Qin, Kin, WQ, WK);
    k_projv<<<dim3(8, 128), dim3(32, 32)>>>(Vin, WV);
    k_qk_mma<<<dim3(32, 32, 8), 256>>>();

    cudaFuncSetAttribute(k_gemm, cudaFuncAttributeMaxDynamicSharedMemorySize, GEMM_SMEM);
    k_gemm<<<dim3(512, 8), 512, GEMM_SMEM>>>();

    k_softmax<<<dim3(NH * NN), 256>>>();

    cudaFuncSetAttribute(k_av, cudaFuncAttributeMaxDynamicSharedMemorySize, AV_SMEM);
    k_av<<<dim3(64, 8), 256, AV_SMEM>>>(out);
}